// round 1
// baseline (speedup 1.0000x reference)
#include <cuda_runtime.h>
#include <math.h>

// Problem constants
#define M_ROWS 4096   // B*S
#define DIM    1024   // H
#define SLEN   1024
#define NH     16
#define HD     64
#define LDA    65     // smem row stride for attention tiles (odd -> bank-friendly)

// Scratch (allocation-free rule: __device__ globals)
__device__ float g_q[M_ROWS * DIM];
__device__ float g_k[M_ROWS * DIM];
__device__ float g_v[M_ROWS * DIM];
__device__ float g_attn[M_ROWS * DIM];

// ---------------------------------------------------------------------------
// GEMM: C[4096,1024] = A[4096,1024] @ W[1024,1024] + bias[1024]
// 128x128 block tile, 8x8 micro tile (split 4+4 at offset 64), KT=16.
// ---------------------------------------------------------------------------
__global__ __launch_bounds__(256, 2)
void gemm_bias_kernel(const float* __restrict__ A, const float* __restrict__ W,
                      const float* __restrict__ bias, float* __restrict__ C) {
    __shared__ float As[16][132];   // transposed A tile: As[k][m]
    __shared__ float Bs[16][132];   // Bs[k][n]

    const int t  = threadIdx.x;           // 0..255
    const int tx = t & 15;
    const int ty = t >> 4;
    const int rowBase = blockIdx.y * 128;
    const int colBase = blockIdx.x * 128;

    float acc[8][8];
#pragma unroll
    for (int i = 0; i < 8; i++)
#pragma unroll
        for (int j = 0; j < 8; j++) acc[i][j] = 0.0f;

    for (int k0 = 0; k0 < DIM; k0 += 16) {
#pragma unroll
        for (int i = 0; i < 2; i++) {
            int f = t + 256 * i;                    // 0..511 float4 slots
            // A: 128 rows x 16 k -> store transposed
            int arow = f >> 2;                       // 4 float4 per row
            int ak   = (f & 3) * 4;
            float4 a4 = *reinterpret_cast<const float4*>(
                &A[(size_t)(rowBase + arow) * DIM + k0 + ak]);
            As[ak + 0][arow] = a4.x;
            As[ak + 1][arow] = a4.y;
            As[ak + 2][arow] = a4.z;
            As[ak + 3][arow] = a4.w;
            // B: 16 k-rows x 128 cols
            int bk = f >> 5;                         // 32 float4 per k-row
            int bc = (f & 31) * 4;
            *reinterpret_cast<float4*>(&Bs[bk][bc]) =
                *reinterpret_cast<const float4*>(
                    &W[(size_t)(k0 + bk) * DIM + colBase + bc]);
        }
        __syncthreads();

#pragma unroll
        for (int kk = 0; kk < 16; kk++) {
            float a[8], b[8];
            *reinterpret_cast<float4*>(&a[0]) =
                *reinterpret_cast<const float4*>(&As[kk][ty * 4]);
            *reinterpret_cast<float4*>(&a[4]) =
                *reinterpret_cast<const float4*>(&As[kk][64 + ty * 4]);
            *reinterpret_cast<float4*>(&b[0]) =
                *reinterpret_cast<const float4*>(&Bs[kk][tx * 4]);
            *reinterpret_cast<float4*>(&b[4]) =
                *reinterpret_cast<const float4*>(&Bs[kk][64 + tx * 4]);
#pragma unroll
            for (int i = 0; i < 8; i++)
#pragma unroll
                for (int j = 0; j < 8; j++)
                    acc[i][j] = fmaf(a[i], b[j], acc[i][j]);
        }
        __syncthreads();
    }

    // Epilogue: + bias, float4 stores
    float bb[8];
    *reinterpret_cast<float4*>(&bb[0]) =
        *reinterpret_cast<const float4*>(&bias[colBase + tx * 4]);
    *reinterpret_cast<float4*>(&bb[4]) =
        *reinterpret_cast<const float4*>(&bias[colBase + 64 + tx * 4]);

#pragma unroll
    for (int i = 0; i < 8; i++) {
        int r = rowBase + ((i < 4) ? (ty * 4 + i) : (64 + ty * 4 + (i - 4)));
        float4 o0 = make_float4(acc[i][0] + bb[0], acc[i][1] + bb[1],
                                acc[i][2] + bb[2], acc[i][3] + bb[3]);
        float4 o1 = make_float4(acc[i][4] + bb[4], acc[i][5] + bb[5],
                                acc[i][6] + bb[6], acc[i][7] + bb[7]);
        *reinterpret_cast<float4*>(&C[(size_t)r * DIM + colBase + tx * 4]) = o0;
        *reinterpret_cast<float4*>(&C[(size_t)r * DIM + colBase + 64 + tx * 4]) = o1;
    }
}

// ---------------------------------------------------------------------------
// Flash attention: block = (64 query rows) x (one head) x (one batch).
// Online softmax in exp2 domain. 4x4 micro-tiles with interleaved column
// ownership (c = cg + 16*j) -> conflict-free scalar LDS in both phases.
// ---------------------------------------------------------------------------
__global__ __launch_bounds__(256, 2)
void attn_kernel(const float* __restrict__ Q, const float* __restrict__ K,
                 const float* __restrict__ V, const unsigned char* __restrict__ mask,
                 float* __restrict__ Out) {
    extern __shared__ float sm[];
    float* Qs = sm;                 // [64][LDA]
    float* Ks = Qs + 64 * LDA;
    float* Vs = Ks + 64 * LDA;
    float* Ps = Vs + 64 * LDA;

    const int t  = threadIdx.x;     // 0..255
    const int cg = t & 15;          // column group
    const int rg = t >> 4;          // row group (16 threads share a row set)
    const int qb = blockIdx.x;
    const int h  = blockIdx.y;
    const int b  = blockIdx.z;

    const int rowBase  = b * SLEN + qb * 64;   // rows into [4096,1024]
    const int colBase  = h * HD;
    const int maskBase = b * SLEN;

    // fold 1/sqrt(64) and log2(e) into Q so softmax uses exp2f
    const float qscale = 0.125f * 1.44269504088896340736f;

    // Load Q tile (once)
#pragma unroll
    for (int i = 0; i < 4; i++) {
        int f   = t + 256 * i;          // 0..1023 float4 slots
        int row = f >> 4;               // 16 float4 per row
        int c4  = (f & 15) * 4;
        float4 q4 = *reinterpret_cast<const float4*>(
            &Q[(size_t)(rowBase + row) * DIM + colBase + c4]);
        Qs[row * LDA + c4 + 0] = q4.x * qscale;
        Qs[row * LDA + c4 + 1] = q4.y * qscale;
        Qs[row * LDA + c4 + 2] = q4.z * qscale;
        Qs[row * LDA + c4 + 3] = q4.w * qscale;
    }

    float m_i[4], l_i[4], acc[4][4];
#pragma unroll
    for (int i = 0; i < 4; i++) {
        m_i[i] = -1e30f;
        l_i[i] = 0.0f;
#pragma unroll
        for (int j = 0; j < 4; j++) acc[i][j] = 0.0f;
    }

    for (int kb = 0; kb < SLEN / 64; kb++) {
        __syncthreads();   // previous iteration's Ps/Vs reads are done
        const int keyBase = b * SLEN + kb * 64;
#pragma unroll
        for (int i = 0; i < 4; i++) {
            int f   = t + 256 * i;
            int row = f >> 4;
            int c4  = (f & 15) * 4;
            float4 k4 = *reinterpret_cast<const float4*>(
                &K[(size_t)(keyBase + row) * DIM + colBase + c4]);
            Ks[row * LDA + c4 + 0] = k4.x;
            Ks[row * LDA + c4 + 1] = k4.y;
            Ks[row * LDA + c4 + 2] = k4.z;
            Ks[row * LDA + c4 + 3] = k4.w;
            float4 v4 = *reinterpret_cast<const float4*>(
                &V[(size_t)(keyBase + row) * DIM + colBase + c4]);
            Vs[row * LDA + c4 + 0] = v4.x;
            Vs[row * LDA + c4 + 1] = v4.y;
            Vs[row * LDA + c4 + 2] = v4.z;
            Vs[row * LDA + c4 + 3] = v4.w;
        }
        __syncthreads();

        // S = Q K^T for this tile: s[i][j] at (row rg+16i, col cg+16j)
        float s[4][4];
#pragma unroll
        for (int i = 0; i < 4; i++)
#pragma unroll
            for (int j = 0; j < 4; j++) s[i][j] = 0.0f;

#pragma unroll 16
        for (int d = 0; d < 64; d++) {
            float qv[4], kv[4];
#pragma unroll
            for (int i = 0; i < 4; i++) qv[i] = Qs[(rg + 16 * i) * LDA + d];
#pragma unroll
            for (int j = 0; j < 4; j++) kv[j] = Ks[(cg + 16 * j) * LDA + d];
#pragma unroll
            for (int i = 0; i < 4; i++)
#pragma unroll
                for (int j = 0; j < 4; j++)
                    s[i][j] = fmaf(qv[i], kv[j], s[i][j]);
        }

        // key-padding mask
#pragma unroll
        for (int j = 0; j < 4; j++) {
            if (mask[maskBase + kb * 64 + cg + 16 * j]) {
#pragma unroll
                for (int i = 0; i < 4; i++) s[i][j] = -1e30f;
            }
        }

        // online softmax update (exp2 domain); reductions over the 16-lane group
#pragma unroll
        for (int i = 0; i < 4; i++) {
            float bm = fmaxf(fmaxf(s[i][0], s[i][1]), fmaxf(s[i][2], s[i][3]));
#pragma unroll
            for (int off = 1; off < 16; off <<= 1)
                bm = fmaxf(bm, __shfl_xor_sync(0xffffffffu, bm, off));
            float mnew = fmaxf(m_i[i], bm);
            float corr = exp2f(m_i[i] - mnew);
            float ps = 0.0f;
#pragma unroll
            for (int j = 0; j < 4; j++) {
                float p = exp2f(s[i][j] - mnew);
                Ps[(rg + 16 * i) * LDA + cg + 16 * j] = p;
                ps += p;
            }
#pragma unroll
            for (int off = 1; off < 16; off <<= 1)
                ps += __shfl_xor_sync(0xffffffffu, ps, off);
            l_i[i] = l_i[i] * corr + ps;
            m_i[i] = mnew;
#pragma unroll
            for (int j = 0; j < 4; j++) acc[i][j] *= corr;
        }
        __syncthreads();   // Ps fully written

        // O += P @ V   (O cols owned as d = cg + 16*j)
#pragma unroll 16
        for (int c = 0; c < 64; c++) {
            float pv[4], vv[4];
#pragma unroll
            for (int i = 0; i < 4; i++) pv[i] = Ps[(rg + 16 * i) * LDA + c];
#pragma unroll
            for (int j = 0; j < 4; j++) vv[j] = Vs[c * LDA + cg + 16 * j];
#pragma unroll
            for (int i = 0; i < 4; i++)
#pragma unroll
                for (int j = 0; j < 4; j++)
                    acc[i][j] = fmaf(pv[i], vv[j], acc[i][j]);
        }
    }

    // finalize and write
#pragma unroll
    for (int i = 0; i < 4; i++) {
        float inv = 1.0f / l_i[i];
        int r = rowBase + rg + 16 * i;
#pragma unroll
        for (int j = 0; j < 4; j++)
            Out[(size_t)r * DIM + colBase + cg + 16 * j] = acc[i][j] * inv;
    }
}

// ---------------------------------------------------------------------------
// Launcher: 3 projection GEMMs -> attention -> output GEMM
// ---------------------------------------------------------------------------
extern "C" void kernel_launch(void* const* d_in, const int* in_sizes, int n_in,
                              void* d_out, int out_size) {
    (void)in_sizes; (void)n_in; (void)out_size;
    const float* x          = (const float*)d_in[0];
    const unsigned char* mk = (const unsigned char*)d_in[1];
    const float* wq = (const float*)d_in[2];
    const float* bq = (const float*)d_in[3];
    const float* wk = (const float*)d_in[4];
    const float* bk = (const float*)d_in[5];
    const float* wv = (const float*)d_in[6];
    const float* bv = (const float*)d_in[7];
    const float* wo = (const float*)d_in[8];
    const float* bo = (const float*)d_in[9];
    float* out = (float*)d_out;

    float *qp, *kp, *vp, *ap;
    cudaGetSymbolAddress((void**)&qp, g_q);
    cudaGetSymbolAddress((void**)&kp, g_k);
    cudaGetSymbolAddress((void**)&vp, g_v);
    cudaGetSymbolAddress((void**)&ap, g_attn);

    dim3 gemm_grid(DIM / 128, M_ROWS / 128);   // (8, 32)
    gemm_bias_kernel<<<gemm_grid, 256>>>(x, wq, bq, qp);
    gemm_bias_kernel<<<gemm_grid, 256>>>(x, wk, bk, kp);
    gemm_bias_kernel<<<gemm_grid, 256>>>(x, wv, bv, vp);

    int smemBytes = 4 * 64 * LDA * (int)sizeof(float);   // 66,560 B
    cudaFuncSetAttribute(attn_kernel,
                         cudaFuncAttributeMaxDynamicSharedMemorySize, smemBytes);
    attn_kernel<<<dim3(SLEN / 64, NH, 4), 256, smemBytes>>>(qp, kp, vp, mk, ap);

    gemm_bias_kernel<<<gemm_grid, 256>>>(ap, wo, bo, out);
}

// round 4
// speedup vs baseline: 1.3853x; 1.3853x over previous
#include <cuda_runtime.h>
#include <cuda_bf16.h>
#include <math.h>
#include <stdint.h>

// Problem constants
#define M_ROWS 4096   // B*S
#define DIM    1024   // H
#define SLEN   1024
#define NH     16
#define HD     64
#define LDA    65     // smem row stride for attention tiles

// ---------------------------------------------------------------------------
// Scratch (allocation-free rule: __device__ globals)
// ---------------------------------------------------------------------------
__device__ float g_q[M_ROWS * DIM];
__device__ float g_k[M_ROWS * DIM];
__device__ float g_v[M_ROWS * DIM];
__device__ float g_attn[M_ROWS * DIM];
__device__ __nv_bfloat16 g_x_hi[M_ROWS * DIM];
__device__ __nv_bfloat16 g_x_lo[M_ROWS * DIM];
__device__ __nv_bfloat16 g_a_hi[M_ROWS * DIM];
__device__ __nv_bfloat16 g_a_lo[M_ROWS * DIM];
// transposed+split weights: [N][K] K-major
__device__ __nv_bfloat16 g_wt_hi[4][DIM * DIM];
__device__ __nv_bfloat16 g_wt_lo[4][DIM * DIM];

// ---------------------------------------------------------------------------
// helpers
// ---------------------------------------------------------------------------
__device__ __forceinline__ uint32_t smem_u32(const void* p) {
    uint32_t a;
    asm("{ .reg .u64 t; cvta.to.shared.u64 t, %1; cvt.u32.u64 %0, t; }"
        : "=r"(a) : "l"(p));
    return a;
}
__device__ __forceinline__ void cp16(uint32_t dst, const void* src) {
    asm volatile("cp.async.cg.shared.global [%0], [%1], 16;"
                 :: "r"(dst), "l"(src));
}
__device__ __forceinline__ void cp_commit() {
    asm volatile("cp.async.commit_group;");
}
template <int N>
__device__ __forceinline__ void cp_wait() {
    asm volatile("cp.async.wait_group %0;" :: "n"(N));
}

__device__ __forceinline__ void mma_bf16(float* c, const uint32_t* a,
                                         const uint32_t* b) {
    asm volatile(
        "mma.sync.aligned.m16n8k16.row.col.f32.bf16.bf16.f32 "
        "{%0,%1,%2,%3}, {%4,%5,%6,%7}, {%8,%9}, {%0,%1,%2,%3};\n"
        : "+f"(c[0]), "+f"(c[1]), "+f"(c[2]), "+f"(c[3])
        : "r"(a[0]), "r"(a[1]), "r"(a[2]), "r"(a[3]), "r"(b[0]), "r"(b[1]));
}

// ---------------------------------------------------------------------------
// Split: x (fp32) -> (hi, lo) bf16 with hi = bf16(x), lo = bf16(x - hi)
// ---------------------------------------------------------------------------
__global__ void split_kernel(const float* __restrict__ in,
                             __nv_bfloat16* __restrict__ hi,
                             __nv_bfloat16* __restrict__ lo, int n4) {
    int i = blockIdx.x * blockDim.x + threadIdx.x;
    if (i >= n4) return;
    float4 x = reinterpret_cast<const float4*>(in)[i];
    __nv_bfloat16 h0 = __float2bfloat16(x.x);
    __nv_bfloat16 h1 = __float2bfloat16(x.y);
    __nv_bfloat16 h2 = __float2bfloat16(x.z);
    __nv_bfloat16 h3 = __float2bfloat16(x.w);
    __nv_bfloat16 l0 = __float2bfloat16(x.x - __bfloat162float(h0));
    __nv_bfloat16 l1 = __float2bfloat16(x.y - __bfloat162float(h1));
    __nv_bfloat16 l2 = __float2bfloat16(x.z - __bfloat162float(h2));
    __nv_bfloat16 l3 = __float2bfloat16(x.w - __bfloat162float(h3));
    __nv_bfloat162* hp = reinterpret_cast<__nv_bfloat162*>(hi);
    __nv_bfloat162* lp = reinterpret_cast<__nv_bfloat162*>(lo);
    hp[2 * i]     = __nv_bfloat162(h0, h1);
    hp[2 * i + 1] = __nv_bfloat162(h2, h3);
    lp[2 * i]     = __nv_bfloat162(l0, l1);
    lp[2 * i + 1] = __nv_bfloat162(l2, l3);
}

// ---------------------------------------------------------------------------
// Transpose + split: W[K][N] fp32 -> Wt_hi[N][K], Wt_lo[N][K] bf16
// ---------------------------------------------------------------------------
__global__ void transpose_split_kernel(const float* __restrict__ W,
                                       __nv_bfloat16* __restrict__ t_hi,
                                       __nv_bfloat16* __restrict__ t_lo) {
    __shared__ float tile[32][33];
    const int tx = threadIdx.x;          // 0..31
    const int ty = threadIdx.y;          // 0..7
    const int k0 = blockIdx.y * 32;
    const int n0 = blockIdx.x * 32;
#pragma unroll
    for (int i = 0; i < 4; i++)
        tile[ty + 8 * i][tx] = W[(size_t)(k0 + ty + 8 * i) * DIM + n0 + tx];
    __syncthreads();
#pragma unroll
    for (int i = 0; i < 4; i++) {
        float v = tile[tx][ty + 8 * i];
        __nv_bfloat16 h = __float2bfloat16(v);
        size_t o = (size_t)(n0 + ty + 8 * i) * DIM + k0 + tx;
        t_hi[o] = h;
        t_lo[o] = __float2bfloat16(v - __bfloat162float(h));
    }
}

// ---------------------------------------------------------------------------
// bf16x3 tensor-core GEMM: C[4096,1024] = A @ W + bias
//   A as (A_hi, A_lo) [M,K] bf16 row-major; W as (B_hi, B_lo) [N,K] bf16.
//   CTA 128x128, BK=32, 3-stage cp.async pipeline, mma.sync m16n8k16.
// ---------------------------------------------------------------------------
#define BM 128
#define BN 128
#define BK 32
#define SH 40                 // smem row stride in bf16 (80 bytes = 20 banks)
#define MAT_BYTES (128 * SH * 2)          // 10240
#define STAGE_BYTES (4 * MAT_BYTES)       // 40960
#define NSTAGE 3
#define GEMM_SMEM (NSTAGE * STAGE_BYTES)  // 122880
#define OFF_AHI 0
#define OFF_ALO MAT_BYTES
#define OFF_BHI (2 * MAT_BYTES)
#define OFF_BLO (3 * MAT_BYTES)

__device__ __forceinline__ void load_stage(uint32_t sdst,
                                           const __nv_bfloat16* __restrict__ A_hi,
                                           const __nv_bfloat16* __restrict__ A_lo,
                                           const __nv_bfloat16* __restrict__ B_hi,
                                           const __nv_bfloat16* __restrict__ B_lo,
                                           int rowBase, int colBase, int k0,
                                           int t) {
    // each matrix tile: 128 rows x 32 bf16 = 512 x 16B chunks
#pragma unroll
    for (int i = 0; i < 2; i++) {
        int id = t + 256 * i;
        int row = id >> 2;
        int c = id & 3;                    // 16B chunk within row
        uint32_t soff = (uint32_t)(row * (SH * 2) + c * 16);
        const __nv_bfloat16* ah = A_hi + (size_t)(rowBase + row) * DIM + k0 + c * 8;
        const __nv_bfloat16* al = A_lo + (size_t)(rowBase + row) * DIM + k0 + c * 8;
        const __nv_bfloat16* bh = B_hi + (size_t)(colBase + row) * DIM + k0 + c * 8;
        const __nv_bfloat16* bl = B_lo + (size_t)(colBase + row) * DIM + k0 + c * 8;
        cp16(sdst + OFF_AHI + soff, ah);
        cp16(sdst + OFF_ALO + soff, al);
        cp16(sdst + OFF_BHI + soff, bh);
        cp16(sdst + OFF_BLO + soff, bl);
    }
    cp_commit();
}

__global__ __launch_bounds__(256, 1)
void mma_gemm_kernel(const __nv_bfloat16* __restrict__ A_hi,
                     const __nv_bfloat16* __restrict__ A_lo,
                     const __nv_bfloat16* __restrict__ B_hi,
                     const __nv_bfloat16* __restrict__ B_lo,
                     const float* __restrict__ bias, float* __restrict__ C) {
    extern __shared__ __align__(128) unsigned char smem[];
    const uint32_t sbase = smem_u32(smem);

    const int t = threadIdx.x;
    const int lane = t & 31;
    const int wid = t >> 5;
    const int warp_m = wid & 3;            // 0..3 -> 32 rows each
    const int warp_n = wid >> 2;           // 0..1 -> 64 cols each
    const int group = lane >> 2;           // 0..7
    const int tcol2 = (lane & 3) * 4;      // byte offset of k-column pair

    const int rowBase = blockIdx.y * BM;
    const int colBase = blockIdx.x * BN;

    float acc[2][8][4];
#pragma unroll
    for (int f = 0; f < 2; f++)
#pragma unroll
        for (int g = 0; g < 8; g++)
#pragma unroll
            for (int r = 0; r < 4; r++) acc[f][g][r] = 0.0f;

    // prologue: fill 3 stages
#pragma unroll
    for (int s = 0; s < NSTAGE; s++)
        load_stage(sbase + s * STAGE_BYTES, A_hi, A_lo, B_hi, B_lo,
                   rowBase, colBase, s * BK, t);

    const int NCHUNK = DIM / BK;   // 32
    for (int c = 0; c < NCHUNK; c++) {
        if (c < NCHUNK - 2) cp_wait<2>();
        else if (c == NCHUNK - 2) cp_wait<1>();
        else cp_wait<0>();
        __syncthreads();

        const unsigned char* stage = smem + (c % NSTAGE) * STAGE_BYTES;
        const unsigned char* pAh = stage + OFF_AHI;
        const unsigned char* pAl = stage + OFF_ALO;
        const unsigned char* pBh = stage + OFF_BHI;
        const unsigned char* pBl = stage + OFF_BLO;

#pragma unroll
        for (int ks = 0; ks < 2; ks++) {
            const int cb = tcol2 + ks * 32;      // byte offset within row
            uint32_t ah[2][4], al[2][4], bh[8][2], bl[8][2];
#pragma unroll
            for (int f = 0; f < 2; f++) {
                int row = warp_m * 32 + f * 16 + group;
                int base = row * (SH * 2) + cb;
                ah[f][0] = *(const uint32_t*)(pAh + base);
                ah[f][1] = *(const uint32_t*)(pAh + base + 8 * (SH * 2));
                ah[f][2] = *(const uint32_t*)(pAh + base + 16);
                ah[f][3] = *(const uint32_t*)(pAh + base + 8 * (SH * 2) + 16);
                al[f][0] = *(const uint32_t*)(pAl + base);
                al[f][1] = *(const uint32_t*)(pAl + base + 8 * (SH * 2));
                al[f][2] = *(const uint32_t*)(pAl + base + 16);
                al[f][3] = *(const uint32_t*)(pAl + base + 8 * (SH * 2) + 16);
            }
#pragma unroll
            for (int g = 0; g < 8; g++) {
                int nrow = warp_n * 64 + g * 8 + group;
                int base = nrow * (SH * 2) + cb;
                bh[g][0] = *(const uint32_t*)(pBh + base);
                bh[g][1] = *(const uint32_t*)(pBh + base + 16);
                bl[g][0] = *(const uint32_t*)(pBl + base);
                bl[g][1] = *(const uint32_t*)(pBl + base + 16);
            }
#pragma unroll
            for (int f = 0; f < 2; f++)
#pragma unroll
                for (int g = 0; g < 8; g++) {
                    mma_bf16(acc[f][g], ah[f], bh[g]);
                    mma_bf16(acc[f][g], ah[f], bl[g]);
                    mma_bf16(acc[f][g], al[f], bh[g]);
                }
        }
        __syncthreads();

        if (c + NSTAGE < NCHUNK)
            load_stage(sbase + (c % NSTAGE) * STAGE_BYTES, A_hi, A_lo, B_hi,
                       B_lo, rowBase, colBase, (c + NSTAGE) * BK, t);
    }

    // epilogue: direct float2 stores + bias
#pragma unroll
    for (int g = 0; g < 8; g++) {
        int col0 = colBase + warp_n * 64 + g * 8 + (lane & 3) * 2;
        float2 bb = *reinterpret_cast<const float2*>(&bias[col0]);
#pragma unroll
        for (int f = 0; f < 2; f++) {
            int r0 = rowBase + warp_m * 32 + f * 16 + group;
            float2 o0 = make_float2(acc[f][g][0] + bb.x, acc[f][g][1] + bb.y);
            float2 o1 = make_float2(acc[f][g][2] + bb.x, acc[f][g][3] + bb.y);
            *reinterpret_cast<float2*>(&C[(size_t)r0 * DIM + col0]) = o0;
            *reinterpret_cast<float2*>(&C[(size_t)(r0 + 8) * DIM + col0]) = o1;
        }
    }
}

// ---------------------------------------------------------------------------
// Flash attention (unchanged from R1 — SIMT, known correct)
// ---------------------------------------------------------------------------
__global__ __launch_bounds__(256, 2)
void attn_kernel(const float* __restrict__ Q, const float* __restrict__ K,
                 const float* __restrict__ V, const unsigned char* __restrict__ mask,
                 float* __restrict__ Out) {
    extern __shared__ float sm[];
    float* Qs = sm;
    float* Ks = Qs + 64 * LDA;
    float* Vs = Ks + 64 * LDA;
    float* Ps = Vs + 64 * LDA;

    const int t = threadIdx.x;
    const int cg = t & 15;
    const int rg = t >> 4;
    const int qb = blockIdx.x;
    const int h = blockIdx.y;
    const int b = blockIdx.z;

    const int rowBase = b * SLEN + qb * 64;
    const int colBase = h * HD;
    const int maskBase = b * SLEN;
    const float qscale = 0.125f * 1.44269504088896340736f;

#pragma unroll
    for (int i = 0; i < 4; i++) {
        int f = t + 256 * i;
        int row = f >> 4;
        int c4 = (f & 15) * 4;
        float4 q4 = *reinterpret_cast<const float4*>(
            &Q[(size_t)(rowBase + row) * DIM + colBase + c4]);
        Qs[row * LDA + c4 + 0] = q4.x * qscale;
        Qs[row * LDA + c4 + 1] = q4.y * qscale;
        Qs[row * LDA + c4 + 2] = q4.z * qscale;
        Qs[row * LDA + c4 + 3] = q4.w * qscale;
    }

    float m_i[4], l_i[4], acc[4][4];
#pragma unroll
    for (int i = 0; i < 4; i++) {
        m_i[i] = -1e30f;
        l_i[i] = 0.0f;
#pragma unroll
        for (int j = 0; j < 4; j++) acc[i][j] = 0.0f;
    }

    for (int kb = 0; kb < SLEN / 64; kb++) {
        __syncthreads();
        const int keyBase = b * SLEN + kb * 64;
#pragma unroll
        for (int i = 0; i < 4; i++) {
            int f = t + 256 * i;
            int row = f >> 4;
            int c4 = (f & 15) * 4;
            float4 k4 = *reinterpret_cast<const float4*>(
                &K[(size_t)(keyBase + row) * DIM + colBase + c4]);
            Ks[row * LDA + c4 + 0] = k4.x;
            Ks[row * LDA + c4 + 1] = k4.y;
            Ks[row * LDA + c4 + 2] = k4.z;
            Ks[row * LDA + c4 + 3] = k4.w;
            float4 v4 = *reinterpret_cast<const float4*>(
                &V[(size_t)(keyBase + row) * DIM + colBase + c4]);
            Vs[row * LDA + c4 + 0] = v4.x;
            Vs[row * LDA + c4 + 1] = v4.y;
            Vs[row * LDA + c4 + 2] = v4.z;
            Vs[row * LDA + c4 + 3] = v4.w;
        }
        __syncthreads();

        float s[4][4];
#pragma unroll
        for (int i = 0; i < 4; i++)
#pragma unroll
            for (int j = 0; j < 4; j++) s[i][j] = 0.0f;

#pragma unroll 16
        for (int d = 0; d < 64; d++) {
            float qv[4], kv[4];
#pragma unroll
            for (int i = 0; i < 4; i++) qv[i] = Qs[(rg + 16 * i) * LDA + d];
#pragma unroll
            for (int j = 0; j < 4; j++) kv[j] = Ks[(cg + 16 * j) * LDA + d];
#pragma unroll
            for (int i = 0; i < 4; i++)
#pragma unroll
                for (int j = 0; j < 4; j++)
                    s[i][j] = fmaf(qv[i], kv[j], s[i][j]);
        }

#pragma unroll
        for (int j = 0; j < 4; j++) {
            if (mask[maskBase + kb * 64 + cg + 16 * j]) {
#pragma unroll
                for (int i = 0; i < 4; i++) s[i][j] = -1e30f;
            }
        }

#pragma unroll
        for (int i = 0; i < 4; i++) {
            float bm = fmaxf(fmaxf(s[i][0], s[i][1]), fmaxf(s[i][2], s[i][3]));
#pragma unroll
            for (int off = 1; off < 16; off <<= 1)
                bm = fmaxf(bm, __shfl_xor_sync(0xffffffffu, bm, off));
            float mnew = fmaxf(m_i[i], bm);
            float corr = exp2f(m_i[i] - mnew);
            float ps = 0.0f;
#pragma unroll
            for (int j = 0; j < 4; j++) {
                float p = exp2f(s[i][j] - mnew);
                Ps[(rg + 16 * i) * LDA + cg + 16 * j] = p;
                ps += p;
            }
#pragma unroll
            for (int off = 1; off < 16; off <<= 1)
                ps += __shfl_xor_sync(0xffffffffu, ps, off);
            l_i[i] = l_i[i] * corr + ps;
            m_i[i] = mnew;
#pragma unroll
            for (int j = 0; j < 4; j++) acc[i][j] *= corr;
        }
        __syncthreads();

#pragma unroll 16
        for (int c = 0; c < 64; c++) {
            float pv[4], vv[4];
#pragma unroll
            for (int i = 0; i < 4; i++) pv[i] = Ps[(rg + 16 * i) * LDA + c];
#pragma unroll
            for (int j = 0; j < 4; j++) vv[j] = Vs[c * LDA + cg + 16 * j];
#pragma unroll
            for (int i = 0; i < 4; i++)
#pragma unroll
                for (int j = 0; j < 4; j++)
                    acc[i][j] = fmaf(pv[i], vv[j], acc[i][j]);
        }
    }

#pragma unroll
    for (int i = 0; i < 4; i++) {
        float inv = 1.0f / l_i[i];
        int r = rowBase + rg + 16 * i;
#pragma unroll
        for (int j = 0; j < 4; j++)
            Out[(size_t)r * DIM + colBase + cg + 16 * j] = acc[i][j] * inv;
    }
}

// ---------------------------------------------------------------------------
// Launcher
// ---------------------------------------------------------------------------
extern "C" void kernel_launch(void* const* d_in, const int* in_sizes, int n_in,
                              void* d_out, int out_size) {
    (void)in_sizes; (void)n_in; (void)out_size;
    const float* x          = (const float*)d_in[0];
    const unsigned char* mk = (const unsigned char*)d_in[1];
    const float* w[4] = {(const float*)d_in[2], (const float*)d_in[4],
                         (const float*)d_in[6], (const float*)d_in[8]};
    const float* bq = (const float*)d_in[3];
    const float* bk = (const float*)d_in[5];
    const float* bv = (const float*)d_in[7];
    const float* bo = (const float*)d_in[9];
    float* out = (float*)d_out;

    float *qp, *kp, *vp, *ap;
    __nv_bfloat16 *xh, *xl, *ah, *al, *wth, *wtl;
    cudaGetSymbolAddress((void**)&qp, g_q);
    cudaGetSymbolAddress((void**)&kp, g_k);
    cudaGetSymbolAddress((void**)&vp, g_v);
    cudaGetSymbolAddress((void**)&ap, g_attn);
    cudaGetSymbolAddress((void**)&xh, g_x_hi);
    cudaGetSymbolAddress((void**)&xl, g_x_lo);
    cudaGetSymbolAddress((void**)&ah, g_a_hi);
    cudaGetSymbolAddress((void**)&al, g_a_lo);
    cudaGetSymbolAddress((void**)&wth, g_wt_hi);
    cudaGetSymbolAddress((void**)&wtl, g_wt_lo);

    // split x; transpose+split weights
    const int n4 = M_ROWS * DIM / 4;
    split_kernel<<<(n4 + 255) / 256, 256>>>(x, xh, xl, n4);
    dim3 tgrid(DIM / 32, DIM / 32);
    for (int i = 0; i < 4; i++)
        transpose_split_kernel<<<tgrid, dim3(32, 8)>>>(
            w[i], wth + (size_t)i * DIM * DIM, wtl + (size_t)i * DIM * DIM);

    cudaFuncSetAttribute(mma_gemm_kernel,
                         cudaFuncAttributeMaxDynamicSharedMemorySize, GEMM_SMEM);
    dim3 ggrid(DIM / BN, M_ROWS / BM);   // (8, 32)

    mma_gemm_kernel<<<ggrid, 256, GEMM_SMEM>>>(
        xh, xl, wth + 0 * (size_t)DIM * DIM, wtl + 0 * (size_t)DIM * DIM, bq, qp);
    mma_gemm_kernel<<<ggrid, 256, GEMM_SMEM>>>(
        xh, xl, wth + 1 * (size_t)DIM * DIM, wtl + 1 * (size_t)DIM * DIM, bk, kp);
    mma_gemm_kernel<<<ggrid, 256, GEMM_SMEM>>>(
        xh, xl, wth + 2 * (size_t)DIM * DIM, wtl + 2 * (size_t)DIM * DIM, bv, vp);

    int smemBytes = 4 * 64 * LDA * (int)sizeof(float);
    cudaFuncSetAttribute(attn_kernel,
                         cudaFuncAttributeMaxDynamicSharedMemorySize, smemBytes);
    attn_kernel<<<dim3(SLEN / 64, NH, 4), 256, smemBytes>>>(qp, kp, vp, mk, ap);

    split_kernel<<<(n4 + 255) / 256, 256>>>(ap, ah, al, n4);
    mma_gemm_kernel<<<ggrid, 256, GEMM_SMEM>>>(
        ah, al, wth + 3 * (size_t)DIM * DIM, wtl + 3 * (size_t)DIM * DIM, bo, out);
}

// round 6
// speedup vs baseline: 2.1608x; 1.5598x over previous
#include <cuda_runtime.h>
#include <cuda_bf16.h>
#include <math.h>
#include <stdint.h>

// Problem constants
#define M_ROWS 4096   // B*S
#define DIM    1024   // H
#define SLEN   1024
#define NH     16
#define HD     64

// ---------------------------------------------------------------------------
// Scratch (allocation-free rule: __device__ globals)
// ---------------------------------------------------------------------------
__device__ __nv_bfloat16 g_x_hi[M_ROWS * DIM];
__device__ __nv_bfloat16 g_x_lo[M_ROWS * DIM];
__device__ __nv_bfloat16 g_q_hi[M_ROWS * DIM];
__device__ __nv_bfloat16 g_q_lo[M_ROWS * DIM];
__device__ __nv_bfloat16 g_k_hi[M_ROWS * DIM];
__device__ __nv_bfloat16 g_k_lo[M_ROWS * DIM];
__device__ __nv_bfloat16 g_v_hi[M_ROWS * DIM];
__device__ __nv_bfloat16 g_v_lo[M_ROWS * DIM];
__device__ __nv_bfloat16 g_vt_hi[M_ROWS * DIM];   // per-batch transposed V
__device__ __nv_bfloat16 g_vt_lo[M_ROWS * DIM];
__device__ __nv_bfloat16 g_a_hi[M_ROWS * DIM];    // attention output (split)
__device__ __nv_bfloat16 g_a_lo[M_ROWS * DIM];
__device__ __nv_bfloat16 g_wt_hi[4][DIM * DIM];   // transposed+split weights [N][K]
__device__ __nv_bfloat16 g_wt_lo[4][DIM * DIM];

// ---------------------------------------------------------------------------
// helpers
// ---------------------------------------------------------------------------
__device__ __forceinline__ uint32_t smem_u32(const void* p) {
    uint32_t a;
    asm("{ .reg .u64 t; cvta.to.shared.u64 t, %1; cvt.u32.u64 %0, t; }"
        : "=r"(a) : "l"(p));
    return a;
}
__device__ __forceinline__ void cp16(uint32_t dst, const void* src) {
    asm volatile("cp.async.cg.shared.global [%0], [%1], 16;"
                 :: "r"(dst), "l"(src));
}
__device__ __forceinline__ void cp_commit() {
    asm volatile("cp.async.commit_group;");
}
template <int N>
__device__ __forceinline__ void cp_wait() {
    asm volatile("cp.async.wait_group %0;" :: "n"(N));
}

__device__ __forceinline__ void mma_bf16(float* c, const uint32_t* a,
                                         const uint32_t* b) {
    asm volatile(
        "mma.sync.aligned.m16n8k16.row.col.f32.bf16.bf16.f32 "
        "{%0,%1,%2,%3}, {%4,%5,%6,%7}, {%8,%9}, {%0,%1,%2,%3};\n"
        : "+f"(c[0]), "+f"(c[1]), "+f"(c[2]), "+f"(c[3])
        : "r"(a[0]), "r"(a[1]), "r"(a[2]), "r"(a[3]), "r"(b[0]), "r"(b[1]));
}

__device__ __forceinline__ uint32_t pack_bf16x2(float x, float y) {
    __nv_bfloat162 h = __floats2bfloat162_rn(x, y);
    return *reinterpret_cast<uint32_t*>(&h);
}
__device__ __forceinline__ float bf16_residual(float x) {
    return x - __bfloat162float(__float2bfloat16(x));
}

// ---------------------------------------------------------------------------
// Split: x (fp32) -> (hi, lo) bf16
// ---------------------------------------------------------------------------
__global__ void split_kernel(const float* __restrict__ in,
                             __nv_bfloat16* __restrict__ hi,
                             __nv_bfloat16* __restrict__ lo, int n4) {
    int i = blockIdx.x * blockDim.x + threadIdx.x;
    if (i >= n4) return;
    float4 x = reinterpret_cast<const float4*>(in)[i];
    uint32_t* hp = reinterpret_cast<uint32_t*>(hi);
    uint32_t* lp = reinterpret_cast<uint32_t*>(lo);
    hp[2 * i]     = pack_bf16x2(x.x, x.y);
    hp[2 * i + 1] = pack_bf16x2(x.z, x.w);
    lp[2 * i]     = pack_bf16x2(bf16_residual(x.x), bf16_residual(x.y));
    lp[2 * i + 1] = pack_bf16x2(bf16_residual(x.z), bf16_residual(x.w));
}

// ---------------------------------------------------------------------------
// Transpose + split: W[K][N] fp32 -> Wt_hi[N][K], Wt_lo[N][K] bf16
// ---------------------------------------------------------------------------
__global__ void transpose_split_kernel(const float* __restrict__ W,
                                       __nv_bfloat16* __restrict__ t_hi,
                                       __nv_bfloat16* __restrict__ t_lo) {
    __shared__ float tile[32][33];
    const int tx = threadIdx.x;
    const int ty = threadIdx.y;
    const int k0 = blockIdx.y * 32;
    const int n0 = blockIdx.x * 32;
#pragma unroll
    for (int i = 0; i < 4; i++)
        tile[ty + 8 * i][tx] = W[(size_t)(k0 + ty + 8 * i) * DIM + n0 + tx];
    __syncthreads();
#pragma unroll
    for (int i = 0; i < 4; i++) {
        float v = tile[tx][ty + 8 * i];
        size_t o = (size_t)(n0 + ty + 8 * i) * DIM + k0 + tx;
        t_hi[o] = __float2bfloat16(v);
        t_lo[o] = __float2bfloat16(bf16_residual(v));
    }
}

// ---------------------------------------------------------------------------
// Per-batch bf16 transpose: vt[b*1024 + col][s] = v[b*1024 + s][col]
// ---------------------------------------------------------------------------
__global__ void transpose_v_kernel(const __nv_bfloat16* __restrict__ vh,
                                   const __nv_bfloat16* __restrict__ vl,
                                   __nv_bfloat16* __restrict__ th,
                                   __nv_bfloat16* __restrict__ tl) {
    __shared__ __nv_bfloat16 tileh[32][33];
    __shared__ __nv_bfloat16 tilel[32][33];
    const int tx = threadIdx.x;
    const int ty = threadIdx.y;
    const int c0 = blockIdx.x * 32;
    const int s0 = blockIdx.y * 32;
    const int b  = blockIdx.z;
    const size_t base = (size_t)b * SLEN * DIM;
#pragma unroll
    for (int i = 0; i < 4; i++) {
        int s = s0 + ty + 8 * i;
        tileh[ty + 8 * i][tx] = vh[base + (size_t)s * DIM + c0 + tx];
        tilel[ty + 8 * i][tx] = vl[base + (size_t)s * DIM + c0 + tx];
    }
    __syncthreads();
#pragma unroll
    for (int i = 0; i < 4; i++) {
        int c = c0 + ty + 8 * i;
        th[base + (size_t)c * SLEN + s0 + tx] = tileh[tx][ty + 8 * i];
        tl[base + (size_t)c * SLEN + s0 + tx] = tilel[tx][ty + 8 * i];
    }
}

// ---------------------------------------------------------------------------
// bf16x3 tensor-core GEMM: C[4096,1024] = A @ W + bias
// OSPLIT=0: fp32 C out; OSPLIT=1: split bf16 (Chi, Clo) out.
// ---------------------------------------------------------------------------
#define BM 128
#define BN 128
#define BK 32
#define SH 40
#define MAT_BYTES (128 * SH * 2)
#define STAGE_BYTES (4 * MAT_BYTES)
#define NSTAGE 3
#define GEMM_SMEM (NSTAGE * STAGE_BYTES)
#define OFF_AHI 0
#define OFF_ALO MAT_BYTES
#define OFF_BHI (2 * MAT_BYTES)
#define OFF_BLO (3 * MAT_BYTES)

__device__ __forceinline__ void load_stage(uint32_t sdst,
                                           const __nv_bfloat16* __restrict__ A_hi,
                                           const __nv_bfloat16* __restrict__ A_lo,
                                           const __nv_bfloat16* __restrict__ B_hi,
                                           const __nv_bfloat16* __restrict__ B_lo,
                                           int rowBase, int colBase, int k0,
                                           int t) {
#pragma unroll
    for (int i = 0; i < 2; i++) {
        int id = t + 256 * i;
        int row = id >> 2;
        int c = id & 3;
        uint32_t soff = (uint32_t)(row * (SH * 2) + c * 16);
        const __nv_bfloat16* ah = A_hi + (size_t)(rowBase + row) * DIM + k0 + c * 8;
        const __nv_bfloat16* al = A_lo + (size_t)(rowBase + row) * DIM + k0 + c * 8;
        const __nv_bfloat16* bh = B_hi + (size_t)(colBase + row) * DIM + k0 + c * 8;
        const __nv_bfloat16* bl = B_lo + (size_t)(colBase + row) * DIM + k0 + c * 8;
        cp16(sdst + OFF_AHI + soff, ah);
        cp16(sdst + OFF_ALO + soff, al);
        cp16(sdst + OFF_BHI + soff, bh);
        cp16(sdst + OFF_BLO + soff, bl);
    }
    cp_commit();
}

template <int OSPLIT>
__global__ __launch_bounds__(256, 1)
void mma_gemm_kernel(const __nv_bfloat16* __restrict__ A_hi,
                     const __nv_bfloat16* __restrict__ A_lo,
                     const __nv_bfloat16* __restrict__ B_hi,
                     const __nv_bfloat16* __restrict__ B_lo,
                     const float* __restrict__ bias, float* __restrict__ C,
                     __nv_bfloat16* __restrict__ Chi,
                     __nv_bfloat16* __restrict__ Clo) {
    extern __shared__ __align__(128) unsigned char smem[];
    const uint32_t sbase = smem_u32(smem);

    const int t = threadIdx.x;
    const int lane = t & 31;
    const int wid = t >> 5;
    const int warp_m = wid & 3;
    const int warp_n = wid >> 2;
    const int group = lane >> 2;
    const int tcol2 = (lane & 3) * 4;

    const int rowBase = blockIdx.y * BM;
    const int colBase = blockIdx.x * BN;

    float acc[2][8][4];
#pragma unroll
    for (int f = 0; f < 2; f++)
#pragma unroll
        for (int g = 0; g < 8; g++)
#pragma unroll
            for (int r = 0; r < 4; r++) acc[f][g][r] = 0.0f;

#pragma unroll
    for (int s = 0; s < NSTAGE; s++)
        load_stage(sbase + s * STAGE_BYTES, A_hi, A_lo, B_hi, B_lo,
                   rowBase, colBase, s * BK, t);

    const int NCHUNK = DIM / BK;
    for (int c = 0; c < NCHUNK; c++) {
        if (c < NCHUNK - 2) cp_wait<2>();
        else if (c == NCHUNK - 2) cp_wait<1>();
        else cp_wait<0>();
        __syncthreads();

        const unsigned char* stage = smem + (c % NSTAGE) * STAGE_BYTES;
        const unsigned char* pAh = stage + OFF_AHI;
        const unsigned char* pAl = stage + OFF_ALO;
        const unsigned char* pBh = stage + OFF_BHI;
        const unsigned char* pBl = stage + OFF_BLO;

#pragma unroll
        for (int ks = 0; ks < 2; ks++) {
            const int cb = tcol2 + ks * 32;
            uint32_t ah[2][4], al[2][4], bh[8][2], bl[8][2];
#pragma unroll
            for (int f = 0; f < 2; f++) {
                int row = warp_m * 32 + f * 16 + group;
                int base = row * (SH * 2) + cb;
                ah[f][0] = *(const uint32_t*)(pAh + base);
                ah[f][1] = *(const uint32_t*)(pAh + base + 8 * (SH * 2));
                ah[f][2] = *(const uint32_t*)(pAh + base + 16);
                ah[f][3] = *(const uint32_t*)(pAh + base + 8 * (SH * 2) + 16);
                al[f][0] = *(const uint32_t*)(pAl + base);
                al[f][1] = *(const uint32_t*)(pAl + base + 8 * (SH * 2));
                al[f][2] = *(const uint32_t*)(pAl + base + 16);
                al[f][3] = *(const uint32_t*)(pAl + base + 8 * (SH * 2) + 16);
            }
#pragma unroll
            for (int g = 0; g < 8; g++) {
                int nrow = warp_n * 64 + g * 8 + group;
                int base = nrow * (SH * 2) + cb;
                bh[g][0] = *(const uint32_t*)(pBh + base);
                bh[g][1] = *(const uint32_t*)(pBh + base + 16);
                bl[g][0] = *(const uint32_t*)(pBl + base);
                bl[g][1] = *(const uint32_t*)(pBl + base + 16);
            }
#pragma unroll
            for (int f = 0; f < 2; f++)
#pragma unroll
                for (int g = 0; g < 8; g++) {
                    mma_bf16(acc[f][g], ah[f], bh[g]);
                    mma_bf16(acc[f][g], ah[f], bl[g]);
                    mma_bf16(acc[f][g], al[f], bh[g]);
                }
        }
        __syncthreads();

        if (c + NSTAGE < NCHUNK)
            load_stage(sbase + (c % NSTAGE) * STAGE_BYTES, A_hi, A_lo, B_hi,
                       B_lo, rowBase, colBase, (c + NSTAGE) * BK, t);
    }

#pragma unroll
    for (int g = 0; g < 8; g++) {
        int col0 = colBase + warp_n * 64 + g * 8 + (lane & 3) * 2;
        float2 bb = *reinterpret_cast<const float2*>(&bias[col0]);
#pragma unroll
        for (int f = 0; f < 2; f++) {
            int r0 = rowBase + warp_m * 32 + f * 16 + group;
            float v0 = acc[f][g][0] + bb.x, v1 = acc[f][g][1] + bb.y;
            float v2 = acc[f][g][2] + bb.x, v3 = acc[f][g][3] + bb.y;
            if (OSPLIT) {
                *reinterpret_cast<uint32_t*>(&Chi[(size_t)r0 * DIM + col0]) =
                    pack_bf16x2(v0, v1);
                *reinterpret_cast<uint32_t*>(&Clo[(size_t)r0 * DIM + col0]) =
                    pack_bf16x2(bf16_residual(v0), bf16_residual(v1));
                *reinterpret_cast<uint32_t*>(&Chi[(size_t)(r0 + 8) * DIM + col0]) =
                    pack_bf16x2(v2, v3);
                *reinterpret_cast<uint32_t*>(&Clo[(size_t)(r0 + 8) * DIM + col0]) =
                    pack_bf16x2(bf16_residual(v2), bf16_residual(v3));
            } else {
                *reinterpret_cast<float2*>(&C[(size_t)r0 * DIM + col0]) =
                    make_float2(v0, v1);
                *reinterpret_cast<float2*>(&C[(size_t)(r0 + 8) * DIM + col0]) =
                    make_float2(v2, v3);
            }
        }
    }
}

// ---------------------------------------------------------------------------
// Tensor-core flash attention (bf16x3 for S=QK^T and O=PV)
// CTA: 128 queries x 1 head x 1 batch. 8 warps x 16 rows. 2-stage K/Vt pipe.
// ---------------------------------------------------------------------------
#define ATQ 128
#define ATK 64
#define ASHB 144                        // smem row stride bytes (72 bf16)
#define AQ_H 0
#define AQ_L (ATQ * ASHB)               // 18432
#define AP_H (2 * ATQ * ASHB)           // 36864
#define AP_L (3 * ATQ * ASHB)           // 55296
#define AST0 (4 * ATQ * ASHB)           // 73728
#define ASTAGE_BYTES (4 * ATK * ASHB)   // 36864 (kh,kl,vth,vtl)
#define AK_H 0
#define AK_L (ATK * ASHB)
#define AV_H (2 * ATK * ASHB)
#define AV_L (3 * ATK * ASHB)
#define AMSK (AST0 + 2 * ASTAGE_BYTES)  // 147456, 2 x 64 floats
#define ATTN_SMEM (AMSK + 2 * 256)      // 147968

// Load stage for key-tile kb into smem slot (kb&1).
// K rows  : b*SLEN + kb*64 + row, cols hcol..hcol+63
// Vt rows : b*SLEN + hcol + row (dims), cols kb*64..kb*64+63 (seq)
__device__ __forceinline__ void attn_load_stage(
    uint32_t sbase,
    const __nv_bfloat16* kh, const __nv_bfloat16* kl,
    const __nv_bfloat16* vth, const __nv_bfloat16* vtl,
    const unsigned char* mk,
    int b, int hcol, int kb, int t) {
    const uint32_t sdst = sbase + AST0 + (uint32_t)(kb & 1) * ASTAGE_BYTES;
    const uint32_t smsk = sbase + AMSK + (uint32_t)(kb & 1) * 256;
    const int keyBase = b * SLEN + kb * ATK;
    const int vtBase  = b * SLEN + hcol;
    const int vtCol   = kb * ATK;
#pragma unroll
    for (int i = 0; i < 2; i++) {
        int id = t + 256 * i;
        int row = id >> 3;
        int c = id & 7;
        uint32_t soff = (uint32_t)(row * ASHB + c * 16);
        cp16(sdst + AK_H + soff,
             kh + (size_t)(keyBase + row) * DIM + hcol + c * 8);
        cp16(sdst + AK_L + soff,
             kl + (size_t)(keyBase + row) * DIM + hcol + c * 8);
        cp16(sdst + AV_H + soff,
             vth + (size_t)(vtBase + row) * SLEN + vtCol + c * 8);
        cp16(sdst + AV_L + soff,
             vtl + (size_t)(vtBase + row) * SLEN + vtCol + c * 8);
    }
    if (t < ATK) {
        float add = mk[b * SLEN + kb * ATK + t] ? -1e30f : 0.0f;
        asm volatile("st.shared.f32 [%0], %1;" :: "r"(smsk + t * 4), "f"(add));
    }
    cp_commit();
}

__global__ __launch_bounds__(256, 1)
void attn_mma_kernel(const __nv_bfloat16* __restrict__ qh,
                     const __nv_bfloat16* __restrict__ ql,
                     const __nv_bfloat16* __restrict__ kh,
                     const __nv_bfloat16* __restrict__ kl,
                     const __nv_bfloat16* __restrict__ vth,
                     const __nv_bfloat16* __restrict__ vtl,
                     const unsigned char* __restrict__ mk,
                     __nv_bfloat16* __restrict__ Oh,
                     __nv_bfloat16* __restrict__ Ol) {
    extern __shared__ __align__(128) unsigned char smem[];
    const uint32_t sbase = smem_u32(smem);

    const int t = threadIdx.x;
    const int lane = t & 31;
    const int w = t >> 5;                 // warp 0..7 -> rows w*16..+15
    const int group = lane >> 2;
    const int tc4 = (lane & 3) * 4;

    const int qb = blockIdx.x;
    const int h  = blockIdx.y;
    const int b  = blockIdx.z;
    const int qBase = b * SLEN + qb * ATQ;
    const int hcol  = h * HD;

    const float qscale = 0.125f * 1.44269504088896340736f;  // 1/8 * log2(e)

    // ---- prologue: Q, then stages 0,1 ----
#pragma unroll
    for (int i = 0; i < 4; i++) {
        int id = t + 256 * i;
        int row = id >> 3;
        int c = id & 7;
        uint32_t soff = (uint32_t)(row * ASHB + c * 16);
        cp16(sbase + AQ_H + soff, qh + (size_t)(qBase + row) * DIM + hcol + c * 8);
        cp16(sbase + AQ_L + soff, ql + (size_t)(qBase + row) * DIM + hcol + c * 8);
    }
    cp_commit();
    attn_load_stage(sbase, kh, kl, vth, vtl, mk, b, hcol, 0, t);
    attn_load_stage(sbase, kh, kl, vth, vtl, mk, b, hcol, 1, t);

    float o[8][4];
    float m_i[2], l_i[2];
#pragma unroll
    for (int g = 0; g < 8; g++)
#pragma unroll
        for (int r = 0; r < 4; r++) o[g][r] = 0.0f;
    m_i[0] = m_i[1] = -1e30f;
    l_i[0] = l_i[1] = 0.0f;

    const int NT = SLEN / ATK;   // 16
    for (int kb = 0; kb < NT; kb++) {
        if (kb == NT - 1) cp_wait<0>(); else cp_wait<1>();
        __syncthreads();

        const unsigned char* stg = smem + AST0 + (kb & 1) * ASTAGE_BYTES;
        const unsigned char* pKh = stg + AK_H;
        const unsigned char* pKl = stg + AK_L;
        const unsigned char* pVh = stg + AV_H;
        const unsigned char* pVl = stg + AV_L;
        const float* madd =
            reinterpret_cast<const float*>(smem + AMSK + (kb & 1) * 256);

        // ---- S = Q K^T (bf16x3) ----
        float s[8][4];
#pragma unroll
        for (int g = 0; g < 8; g++)
#pragma unroll
            for (int r = 0; r < 4; r++) s[g][r] = 0.0f;

        const unsigned char* pQh = smem + AQ_H;
        const unsigned char* pQl = smem + AQ_L;
#pragma unroll
        for (int k = 0; k < 4; k++) {
            const int cb = tc4 + k * 32;
            uint32_t ah[4], al[4];
            int abase = (w * 16 + group) * ASHB + cb;
            ah[0] = *(const uint32_t*)(pQh + abase);
            ah[1] = *(const uint32_t*)(pQh + abase + 8 * ASHB);
            ah[2] = *(const uint32_t*)(pQh + abase + 16);
            ah[3] = *(const uint32_t*)(pQh + abase + 8 * ASHB + 16);
            al[0] = *(const uint32_t*)(pQl + abase);
            al[1] = *(const uint32_t*)(pQl + abase + 8 * ASHB);
            al[2] = *(const uint32_t*)(pQl + abase + 16);
            al[3] = *(const uint32_t*)(pQl + abase + 8 * ASHB + 16);
#pragma unroll
            for (int g = 0; g < 8; g++) {
                int bbase = (g * 8 + group) * ASHB + cb;
                uint32_t bh[2], bl[2];
                bh[0] = *(const uint32_t*)(pKh + bbase);
                bh[1] = *(const uint32_t*)(pKh + bbase + 16);
                bl[0] = *(const uint32_t*)(pKl + bbase);
                bl[1] = *(const uint32_t*)(pKl + bbase + 16);
                mma_bf16(s[g], ah, bh);
                mma_bf16(s[g], ah, bl);
                mma_bf16(s[g], al, bh);
            }
        }

        // ---- scale + mask + online softmax ----
#pragma unroll
        for (int g = 0; g < 8; g++) {
            float2 ma = *reinterpret_cast<const float2*>(
                &madd[g * 8 + (lane & 3) * 2]);
            s[g][0] = fmaf(s[g][0], qscale, ma.x);
            s[g][1] = fmaf(s[g][1], qscale, ma.y);
            s[g][2] = fmaf(s[g][2], qscale, ma.x);
            s[g][3] = fmaf(s[g][3], qscale, ma.y);
        }
        float mx0 = -1e30f, mx1 = -1e30f;
#pragma unroll
        for (int g = 0; g < 8; g++) {
            mx0 = fmaxf(mx0, fmaxf(s[g][0], s[g][1]));
            mx1 = fmaxf(mx1, fmaxf(s[g][2], s[g][3]));
        }
        mx0 = fmaxf(mx0, __shfl_xor_sync(0xffffffffu, mx0, 1));
        mx0 = fmaxf(mx0, __shfl_xor_sync(0xffffffffu, mx0, 2));
        mx1 = fmaxf(mx1, __shfl_xor_sync(0xffffffffu, mx1, 1));
        mx1 = fmaxf(mx1, __shfl_xor_sync(0xffffffffu, mx1, 2));
        float mn0 = fmaxf(m_i[0], mx0);
        float mn1 = fmaxf(m_i[1], mx1);
        float corr0 = exp2f(m_i[0] - mn0);
        float corr1 = exp2f(m_i[1] - mn1);
        m_i[0] = mn0; m_i[1] = mn1;

        float sum0 = 0.0f, sum1 = 0.0f;
        const int r0 = w * 16 + group;
        const int pcol = (lane & 3) * 4;
#pragma unroll
        for (int g = 0; g < 8; g++) {
            float p0 = exp2f(s[g][0] - mn0);
            float p1 = exp2f(s[g][1] - mn0);
            float p2 = exp2f(s[g][2] - mn1);
            float p3 = exp2f(s[g][3] - mn1);
            sum0 += p0 + p1;
            sum1 += p2 + p3;
            uint32_t poff0 = (uint32_t)(r0 * ASHB + g * 16 + pcol);
            uint32_t poff1 = (uint32_t)((r0 + 8) * ASHB + g * 16 + pcol);
            *reinterpret_cast<uint32_t*>(smem + AP_H + poff0) = pack_bf16x2(p0, p1);
            *reinterpret_cast<uint32_t*>(smem + AP_L + poff0) =
                pack_bf16x2(bf16_residual(p0), bf16_residual(p1));
            *reinterpret_cast<uint32_t*>(smem + AP_H + poff1) = pack_bf16x2(p2, p3);
            *reinterpret_cast<uint32_t*>(smem + AP_L + poff1) =
                pack_bf16x2(bf16_residual(p2), bf16_residual(p3));
        }
        sum0 += __shfl_xor_sync(0xffffffffu, sum0, 1);
        sum0 += __shfl_xor_sync(0xffffffffu, sum0, 2);
        sum1 += __shfl_xor_sync(0xffffffffu, sum1, 1);
        sum1 += __shfl_xor_sync(0xffffffffu, sum1, 2);
        l_i[0] = l_i[0] * corr0 + sum0;
        l_i[1] = l_i[1] * corr1 + sum1;
#pragma unroll
        for (int g = 0; g < 8; g++) {
            o[g][0] *= corr0; o[g][1] *= corr0;
            o[g][2] *= corr1; o[g][3] *= corr1;
        }
        __syncthreads();   // P visible; all warps finished reading K

        // ---- O += P Vt (bf16x3) ----
        const unsigned char* pPh = smem + AP_H;
        const unsigned char* pPl = smem + AP_L;
#pragma unroll
        for (int k = 0; k < 4; k++) {
            const int cb = tc4 + k * 32;
            uint32_t ah[4], al[4];
            int abase = (w * 16 + group) * ASHB + cb;
            ah[0] = *(const uint32_t*)(pPh + abase);
            ah[1] = *(const uint32_t*)(pPh + abase + 8 * ASHB);
            ah[2] = *(const uint32_t*)(pPh + abase + 16);
            ah[3] = *(const uint32_t*)(pPh + abase + 8 * ASHB + 16);
            al[0] = *(const uint32_t*)(pPl + abase);
            al[1] = *(const uint32_t*)(pPl + abase + 8 * ASHB);
            al[2] = *(const uint32_t*)(pPl + abase + 16);
            al[3] = *(const uint32_t*)(pPl + abase + 8 * ASHB + 16);
#pragma unroll
            for (int g = 0; g < 8; g++) {
                int bbase = (g * 8 + group) * ASHB + cb;
                uint32_t bh[2], bl[2];
                bh[0] = *(const uint32_t*)(pVh + bbase);
                bh[1] = *(const uint32_t*)(pVh + bbase + 16);
                bl[0] = *(const uint32_t*)(pVl + bbase);
                bl[1] = *(const uint32_t*)(pVl + bbase + 16);
                mma_bf16(o[g], ah, bh);
                mma_bf16(o[g], ah, bl);
                mma_bf16(o[g], al, bh);
            }
        }
        __syncthreads();   // done reading stage + P

        if (kb + 2 < NT)
            attn_load_stage(sbase, kh, kl, vth, vtl, mk, b, hcol, kb + 2, t);
    }

    // ---- finalize: O / l, split-store bf16 ----
    float inv0 = 1.0f / l_i[0];
    float inv1 = 1.0f / l_i[1];
    const int gr0 = qBase + w * 16 + group;
#pragma unroll
    for (int g = 0; g < 8; g++) {
        int col = hcol + g * 8 + (lane & 3) * 2;
        float v0 = o[g][0] * inv0, v1 = o[g][1] * inv0;
        float v2 = o[g][2] * inv1, v3 = o[g][3] * inv1;
        *reinterpret_cast<uint32_t*>(&Oh[(size_t)gr0 * DIM + col]) =
            pack_bf16x2(v0, v1);
        *reinterpret_cast<uint32_t*>(&Ol[(size_t)gr0 * DIM + col]) =
            pack_bf16x2(bf16_residual(v0), bf16_residual(v1));
        *reinterpret_cast<uint32_t*>(&Oh[(size_t)(gr0 + 8) * DIM + col]) =
            pack_bf16x2(v2, v3);
        *reinterpret_cast<uint32_t*>(&Ol[(size_t)(gr0 + 8) * DIM + col]) =
            pack_bf16x2(bf16_residual(v2), bf16_residual(v3));
    }
}

// ---------------------------------------------------------------------------
// Launcher
// ---------------------------------------------------------------------------
extern "C" void kernel_launch(void* const* d_in, const int* in_sizes, int n_in,
                              void* d_out, int out_size) {
    (void)in_sizes; (void)n_in; (void)out_size;
    const float* x          = (const float*)d_in[0];
    const unsigned char* mk = (const unsigned char*)d_in[1];
    const float* w[4] = {(const float*)d_in[2], (const float*)d_in[4],
                         (const float*)d_in[6], (const float*)d_in[8]};
    const float* bq = (const float*)d_in[3];
    const float* bk = (const float*)d_in[5];
    const float* bv = (const float*)d_in[7];
    const float* bo = (const float*)d_in[9];
    float* out = (float*)d_out;

    __nv_bfloat16 *xh, *xl, *qhp, *qlp, *khp, *klp, *vhp, *vlp;
    __nv_bfloat16 *vth, *vtl, *ah, *al, *wth, *wtl;
    cudaGetSymbolAddress((void**)&xh, g_x_hi);
    cudaGetSymbolAddress((void**)&xl, g_x_lo);
    cudaGetSymbolAddress((void**)&qhp, g_q_hi);
    cudaGetSymbolAddress((void**)&qlp, g_q_lo);
    cudaGetSymbolAddress((void**)&khp, g_k_hi);
    cudaGetSymbolAddress((void**)&klp, g_k_lo);
    cudaGetSymbolAddress((void**)&vhp, g_v_hi);
    cudaGetSymbolAddress((void**)&vlp, g_v_lo);
    cudaGetSymbolAddress((void**)&vth, g_vt_hi);
    cudaGetSymbolAddress((void**)&vtl, g_vt_lo);
    cudaGetSymbolAddress((void**)&ah, g_a_hi);
    cudaGetSymbolAddress((void**)&al, g_a_lo);
    cudaGetSymbolAddress((void**)&wth, g_wt_hi);
    cudaGetSymbolAddress((void**)&wtl, g_wt_lo);

    const int n4 = M_ROWS * DIM / 4;
    split_kernel<<<(n4 + 255) / 256, 256>>>(x, xh, xl, n4);
    dim3 tgrid(DIM / 32, DIM / 32);
    for (int i = 0; i < 4; i++)
        transpose_split_kernel<<<tgrid, dim3(32, 8)>>>(
            w[i], wth + (size_t)i * DIM * DIM, wtl + (size_t)i * DIM * DIM);

    cudaFuncSetAttribute(mma_gemm_kernel<0>,
                         cudaFuncAttributeMaxDynamicSharedMemorySize, GEMM_SMEM);
    cudaFuncSetAttribute(mma_gemm_kernel<1>,
                         cudaFuncAttributeMaxDynamicSharedMemorySize, GEMM_SMEM);
    dim3 ggrid(DIM / BN, M_ROWS / BM);

    mma_gemm_kernel<1><<<ggrid, 256, GEMM_SMEM>>>(
        xh, xl, wth + 0 * (size_t)DIM * DIM, wtl + 0 * (size_t)DIM * DIM, bq,
        nullptr, qhp, qlp);
    mma_gemm_kernel<1><<<ggrid, 256, GEMM_SMEM>>>(
        xh, xl, wth + 1 * (size_t)DIM * DIM, wtl + 1 * (size_t)DIM * DIM, bk,
        nullptr, khp, klp);
    mma_gemm_kernel<1><<<ggrid, 256, GEMM_SMEM>>>(
        xh, xl, wth + 2 * (size_t)DIM * DIM, wtl + 2 * (size_t)DIM * DIM, bv,
        nullptr, vhp, vlp);

    transpose_v_kernel<<<dim3(32, 32, 4), dim3(32, 8)>>>(vhp, vlp, vth, vtl);

    cudaFuncSetAttribute(attn_mma_kernel,
                         cudaFuncAttributeMaxDynamicSharedMemorySize, ATTN_SMEM);
    attn_mma_kernel<<<dim3(SLEN / ATQ, NH, 4), 256, ATTN_SMEM>>>(
        qhp, qlp, khp, klp, vth, vtl, mk, ah, al);

    mma_gemm_kernel<0><<<ggrid, 256, GEMM_SMEM>>>(
        ah, al, wth + 3 * (size_t)DIM * DIM, wtl + 3 * (size_t)DIM * DIM, bo,
        out, nullptr, nullptr);
}

// round 8
// speedup vs baseline: 2.2915x; 1.0605x over previous
#include <cuda_runtime.h>
#include <cuda_bf16.h>
#include <math.h>
#include <stdint.h>

// Problem constants
#define M_ROWS 4096   // B*S
#define DIM    1024   // H
#define SLEN   1024
#define NH     16
#define HD     64

// ---------------------------------------------------------------------------
// Scratch (allocation-free rule: __device__ globals)
// ---------------------------------------------------------------------------
__device__ __nv_bfloat16 g_x_hi[M_ROWS * DIM];
__device__ __nv_bfloat16 g_x_lo[M_ROWS * DIM];
__device__ __nv_bfloat16 g_q_hi[M_ROWS * DIM];
__device__ __nv_bfloat16 g_q_lo[M_ROWS * DIM];
__device__ __nv_bfloat16 g_k_hi[M_ROWS * DIM];
__device__ __nv_bfloat16 g_k_lo[M_ROWS * DIM];
__device__ __nv_bfloat16 g_v_hi[M_ROWS * DIM];
__device__ __nv_bfloat16 g_v_lo[M_ROWS * DIM];
__device__ __nv_bfloat16 g_vt_hi[M_ROWS * DIM];   // per-batch transposed V
__device__ __nv_bfloat16 g_vt_lo[M_ROWS * DIM];
__device__ __nv_bfloat16 g_a_hi[M_ROWS * DIM];    // attention output (split)
__device__ __nv_bfloat16 g_a_lo[M_ROWS * DIM];
__device__ __nv_bfloat16 g_wt_hi[4][DIM * DIM];   // transposed+split weights [N][K]
__device__ __nv_bfloat16 g_wt_lo[4][DIM * DIM];

// ---------------------------------------------------------------------------
// helpers
// ---------------------------------------------------------------------------
__device__ __forceinline__ uint32_t smem_u32(const void* p) {
    uint32_t a;
    asm("{ .reg .u64 t; cvta.to.shared.u64 t, %1; cvt.u32.u64 %0, t; }"
        : "=r"(a) : "l"(p));
    return a;
}
__device__ __forceinline__ void cp16(uint32_t dst, const void* src) {
    asm volatile("cp.async.cg.shared.global [%0], [%1], 16;"
                 :: "r"(dst), "l"(src));
}
__device__ __forceinline__ void cp_commit() {
    asm volatile("cp.async.commit_group;");
}
template <int N>
__device__ __forceinline__ void cp_wait() {
    asm volatile("cp.async.wait_group %0;" :: "n"(N));
}

__device__ __forceinline__ void mma_bf16(float* c, const uint32_t* a,
                                         const uint32_t* b) {
    asm volatile(
        "mma.sync.aligned.m16n8k16.row.col.f32.bf16.bf16.f32 "
        "{%0,%1,%2,%3}, {%4,%5,%6,%7}, {%8,%9}, {%0,%1,%2,%3};\n"
        : "+f"(c[0]), "+f"(c[1]), "+f"(c[2]), "+f"(c[3])
        : "r"(a[0]), "r"(a[1]), "r"(a[2]), "r"(a[3]), "r"(b[0]), "r"(b[1]));
}

__device__ __forceinline__ uint32_t pack_bf16x2(float x, float y) {
    __nv_bfloat162 h = __floats2bfloat162_rn(x, y);
    return *reinterpret_cast<uint32_t*>(&h);
}
__device__ __forceinline__ float bf16_residual(float x) {
    return x - __bfloat162float(__float2bfloat16(x));
}

// ---------------------------------------------------------------------------
// Split: x (fp32) -> (hi, lo) bf16
// ---------------------------------------------------------------------------
__global__ void split_kernel(const float* __restrict__ in,
                             __nv_bfloat16* __restrict__ hi,
                             __nv_bfloat16* __restrict__ lo, int n4) {
    int i = blockIdx.x * blockDim.x + threadIdx.x;
    if (i >= n4) return;
    float4 x = reinterpret_cast<const float4*>(in)[i];
    uint32_t* hp = reinterpret_cast<uint32_t*>(hi);
    uint32_t* lp = reinterpret_cast<uint32_t*>(lo);
    hp[2 * i]     = pack_bf16x2(x.x, x.y);
    hp[2 * i + 1] = pack_bf16x2(x.z, x.w);
    lp[2 * i]     = pack_bf16x2(bf16_residual(x.x), bf16_residual(x.y));
    lp[2 * i + 1] = pack_bf16x2(bf16_residual(x.z), bf16_residual(x.w));
}

// ---------------------------------------------------------------------------
// Transpose + split: W[K][N] fp32 -> Wt_hi[N][K], Wt_lo[N][K] bf16
// ---------------------------------------------------------------------------
__global__ void transpose_split_kernel(const float* __restrict__ W,
                                       __nv_bfloat16* __restrict__ t_hi,
                                       __nv_bfloat16* __restrict__ t_lo) {
    __shared__ float tile[32][33];
    const int tx = threadIdx.x;
    const int ty = threadIdx.y;
    const int k0 = blockIdx.y * 32;
    const int n0 = blockIdx.x * 32;
#pragma unroll
    for (int i = 0; i < 4; i++)
        tile[ty + 8 * i][tx] = W[(size_t)(k0 + ty + 8 * i) * DIM + n0 + tx];
    __syncthreads();
#pragma unroll
    for (int i = 0; i < 4; i++) {
        float v = tile[tx][ty + 8 * i];
        size_t o = (size_t)(n0 + ty + 8 * i) * DIM + k0 + tx;
        t_hi[o] = __float2bfloat16(v);
        t_lo[o] = __float2bfloat16(bf16_residual(v));
    }
}

// ---------------------------------------------------------------------------
// Per-batch bf16 transpose: vt[b*1024 + col][s] = v[b*1024 + s][col]
// ---------------------------------------------------------------------------
__global__ void transpose_v_kernel(const __nv_bfloat16* __restrict__ vh,
                                   const __nv_bfloat16* __restrict__ vl,
                                   __nv_bfloat16* __restrict__ th,
                                   __nv_bfloat16* __restrict__ tl) {
    __shared__ __nv_bfloat16 tileh[32][33];
    __shared__ __nv_bfloat16 tilel[32][33];
    const int tx = threadIdx.x;
    const int ty = threadIdx.y;
    const int c0 = blockIdx.x * 32;
    const int s0 = blockIdx.y * 32;
    const int b  = blockIdx.z;
    const size_t base = (size_t)b * SLEN * DIM;
#pragma unroll
    for (int i = 0; i < 4; i++) {
        int s = s0 + ty + 8 * i;
        tileh[ty + 8 * i][tx] = vh[base + (size_t)s * DIM + c0 + tx];
        tilel[ty + 8 * i][tx] = vl[base + (size_t)s * DIM + c0 + tx];
    }
    __syncthreads();
#pragma unroll
    for (int i = 0; i < 4; i++) {
        int c = c0 + ty + 8 * i;
        th[base + (size_t)c * SLEN + s0 + tx] = tileh[tx][ty + 8 * i];
        tl[base + (size_t)c * SLEN + s0 + tx] = tilel[tx][ty + 8 * i];
    }
}

// ---------------------------------------------------------------------------
// bf16x3 tensor-core GEMM: C[4096,1024] = A @ W + bias
// OSPLIT=0: fp32 C out; OSPLIT=1: split bf16 (Chi, Clo) out.
// ---------------------------------------------------------------------------
#define BM 128
#define BN 128
#define BK 32
#define SH 40
#define MAT_BYTES (128 * SH * 2)
#define STAGE_BYTES (4 * MAT_BYTES)
#define NSTAGE 3
#define GEMM_SMEM (NSTAGE * STAGE_BYTES)
#define OFF_AHI 0
#define OFF_ALO MAT_BYTES
#define OFF_BHI (2 * MAT_BYTES)
#define OFF_BLO (3 * MAT_BYTES)

__device__ __forceinline__ void load_stage(uint32_t sdst,
                                           const __nv_bfloat16* __restrict__ A_hi,
                                           const __nv_bfloat16* __restrict__ A_lo,
                                           const __nv_bfloat16* __restrict__ B_hi,
                                           const __nv_bfloat16* __restrict__ B_lo,
                                           int rowBase, int colBase, int k0,
                                           int t) {
#pragma unroll
    for (int i = 0; i < 2; i++) {
        int id = t + 256 * i;
        int row = id >> 2;
        int c = id & 3;
        uint32_t soff = (uint32_t)(row * (SH * 2) + c * 16);
        const __nv_bfloat16* ah = A_hi + (size_t)(rowBase + row) * DIM + k0 + c * 8;
        const __nv_bfloat16* al = A_lo + (size_t)(rowBase + row) * DIM + k0 + c * 8;
        const __nv_bfloat16* bh = B_hi + (size_t)(colBase + row) * DIM + k0 + c * 8;
        const __nv_bfloat16* bl = B_lo + (size_t)(colBase + row) * DIM + k0 + c * 8;
        cp16(sdst + OFF_AHI + soff, ah);
        cp16(sdst + OFF_ALO + soff, al);
        cp16(sdst + OFF_BHI + soff, bh);
        cp16(sdst + OFF_BLO + soff, bl);
    }
    cp_commit();
}

template <int OSPLIT>
__global__ __launch_bounds__(256, 1)
void mma_gemm_kernel(const __nv_bfloat16* __restrict__ A_hi,
                     const __nv_bfloat16* __restrict__ A_lo,
                     const __nv_bfloat16* __restrict__ B_hi,
                     const __nv_bfloat16* __restrict__ B_lo,
                     const float* __restrict__ bias, float* __restrict__ C,
                     __nv_bfloat16* __restrict__ Chi,
                     __nv_bfloat16* __restrict__ Clo) {
    extern __shared__ __align__(128) unsigned char smem[];
    const uint32_t sbase = smem_u32(smem);

    const int t = threadIdx.x;
    const int lane = t & 31;
    const int wid = t >> 5;
    const int warp_m = wid & 3;
    const int warp_n = wid >> 2;
    const int group = lane >> 2;
    const int tcol2 = (lane & 3) * 4;

    const int rowBase = blockIdx.y * BM;
    const int colBase = blockIdx.x * BN;

    float acc[2][8][4];
#pragma unroll
    for (int f = 0; f < 2; f++)
#pragma unroll
        for (int g = 0; g < 8; g++)
#pragma unroll
            for (int r = 0; r < 4; r++) acc[f][g][r] = 0.0f;

#pragma unroll
    for (int s = 0; s < NSTAGE; s++)
        load_stage(sbase + s * STAGE_BYTES, A_hi, A_lo, B_hi, B_lo,
                   rowBase, colBase, s * BK, t);

    const int NCHUNK = DIM / BK;
    for (int c = 0; c < NCHUNK; c++) {
        if (c < NCHUNK - 2) cp_wait<2>();
        else if (c == NCHUNK - 2) cp_wait<1>();
        else cp_wait<0>();
        __syncthreads();

        const unsigned char* stage = smem + (c % NSTAGE) * STAGE_BYTES;
        const unsigned char* pAh = stage + OFF_AHI;
        const unsigned char* pAl = stage + OFF_ALO;
        const unsigned char* pBh = stage + OFF_BHI;
        const unsigned char* pBl = stage + OFF_BLO;

#pragma unroll
        for (int ks = 0; ks < 2; ks++) {
            const int cb = tcol2 + ks * 32;
            uint32_t ah[2][4], al[2][4], bh[8][2], bl[8][2];
#pragma unroll
            for (int f = 0; f < 2; f++) {
                int row = warp_m * 32 + f * 16 + group;
                int base = row * (SH * 2) + cb;
                ah[f][0] = *(const uint32_t*)(pAh + base);
                ah[f][1] = *(const uint32_t*)(pAh + base + 8 * (SH * 2));
                ah[f][2] = *(const uint32_t*)(pAh + base + 16);
                ah[f][3] = *(const uint32_t*)(pAh + base + 8 * (SH * 2) + 16);
                al[f][0] = *(const uint32_t*)(pAl + base);
                al[f][1] = *(const uint32_t*)(pAl + base + 8 * (SH * 2));
                al[f][2] = *(const uint32_t*)(pAl + base + 16);
                al[f][3] = *(const uint32_t*)(pAl + base + 8 * (SH * 2) + 16);
            }
#pragma unroll
            for (int g = 0; g < 8; g++) {
                int nrow = warp_n * 64 + g * 8 + group;
                int base = nrow * (SH * 2) + cb;
                bh[g][0] = *(const uint32_t*)(pBh + base);
                bh[g][1] = *(const uint32_t*)(pBh + base + 16);
                bl[g][0] = *(const uint32_t*)(pBl + base);
                bl[g][1] = *(const uint32_t*)(pBl + base + 16);
            }
#pragma unroll
            for (int f = 0; f < 2; f++)
#pragma unroll
                for (int g = 0; g < 8; g++) {
                    mma_bf16(acc[f][g], ah[f], bh[g]);
                    mma_bf16(acc[f][g], ah[f], bl[g]);
                    mma_bf16(acc[f][g], al[f], bh[g]);
                }
        }
        __syncthreads();

        if (c + NSTAGE < NCHUNK)
            load_stage(sbase + (c % NSTAGE) * STAGE_BYTES, A_hi, A_lo, B_hi,
                       B_lo, rowBase, colBase, (c + NSTAGE) * BK, t);
    }

#pragma unroll
    for (int g = 0; g < 8; g++) {
        int col0 = colBase + warp_n * 64 + g * 8 + (lane & 3) * 2;
        float2 bb = *reinterpret_cast<const float2*>(&bias[col0]);
#pragma unroll
        for (int f = 0; f < 2; f++) {
            int r0 = rowBase + warp_m * 32 + f * 16 + group;
            float v0 = acc[f][g][0] + bb.x, v1 = acc[f][g][1] + bb.y;
            float v2 = acc[f][g][2] + bb.x, v3 = acc[f][g][3] + bb.y;
            if (OSPLIT) {
                *reinterpret_cast<uint32_t*>(&Chi[(size_t)r0 * DIM + col0]) =
                    pack_bf16x2(v0, v1);
                *reinterpret_cast<uint32_t*>(&Clo[(size_t)r0 * DIM + col0]) =
                    pack_bf16x2(bf16_residual(v0), bf16_residual(v1));
                *reinterpret_cast<uint32_t*>(&Chi[(size_t)(r0 + 8) * DIM + col0]) =
                    pack_bf16x2(v2, v3);
                *reinterpret_cast<uint32_t*>(&Clo[(size_t)(r0 + 8) * DIM + col0]) =
                    pack_bf16x2(bf16_residual(v2), bf16_residual(v3));
            } else {
                *reinterpret_cast<float2*>(&C[(size_t)r0 * DIM + col0]) =
                    make_float2(v0, v1);
                *reinterpret_cast<float2*>(&C[(size_t)(r0 + 8) * DIM + col0]) =
                    make_float2(v2, v3);
            }
        }
    }
}

// ---------------------------------------------------------------------------
// Tensor-core flash attention, register-resident P (FA2-style):
// the S accumulator fragment layout == PV A-fragment layout, so P (hi+lo)
// is packed in registers; no P smem round-trip. smem = Q + 2 stages + mask
// = 111 KB -> 2 CTAs/SM.
// ---------------------------------------------------------------------------
#define ATQ 128
#define ATK 64
#define ASHB 144                        // smem row stride bytes (72 bf16)
#define AQ_H 0
#define AQ_L (ATQ * ASHB)               // 18432
#define AST0 (2 * ATQ * ASHB)           // 36864
#define ASTAGE_BYTES (4 * ATK * ASHB)   // 36864 (kh,kl,vth,vtl)
#define AK_H 0
#define AK_L (ATK * ASHB)
#define AV_H (2 * ATK * ASHB)
#define AV_L (3 * ATK * ASHB)
#define AMSK (AST0 + 2 * ASTAGE_BYTES)  // 110592, 2 x 64 floats
#define ATTN_SMEM (AMSK + 2 * 256)      // 111104

// Load stage for key-tile kb into smem slot (kb&1).
__device__ __forceinline__ void attn_load_stage(
    uint32_t sbase,
    const __nv_bfloat16* kh, const __nv_bfloat16* kl,
    const __nv_bfloat16* vth, const __nv_bfloat16* vtl,
    const unsigned char* mk,
    int b, int hcol, int kb, int t) {
    const uint32_t sdst = sbase + AST0 + (uint32_t)(kb & 1) * ASTAGE_BYTES;
    const uint32_t smsk = sbase + AMSK + (uint32_t)(kb & 1) * 256;
    const int keyBase = b * SLEN + kb * ATK;
    const int vtBase  = b * SLEN + hcol;
    const int vtCol   = kb * ATK;
#pragma unroll
    for (int i = 0; i < 2; i++) {
        int id = t + 256 * i;
        int row = id >> 3;
        int c = id & 7;
        uint32_t soff = (uint32_t)(row * ASHB + c * 16);
        cp16(sdst + AK_H + soff,
             kh + (size_t)(keyBase + row) * DIM + hcol + c * 8);
        cp16(sdst + AK_L + soff,
             kl + (size_t)(keyBase + row) * DIM + hcol + c * 8);
        cp16(sdst + AV_H + soff,
             vth + (size_t)(vtBase + row) * SLEN + vtCol + c * 8);
        cp16(sdst + AV_L + soff,
             vtl + (size_t)(vtBase + row) * SLEN + vtCol + c * 8);
    }
    if (t < ATK) {
        float add = mk[b * SLEN + kb * ATK + t] ? -1e30f : 0.0f;
        asm volatile("st.shared.f32 [%0], %1;" :: "r"(smsk + t * 4), "f"(add));
    }
    cp_commit();
}

__global__ __launch_bounds__(256, 2)
void attn_mma_kernel(const __nv_bfloat16* __restrict__ qh,
                     const __nv_bfloat16* __restrict__ ql,
                     const __nv_bfloat16* __restrict__ kh,
                     const __nv_bfloat16* __restrict__ kl,
                     const __nv_bfloat16* __restrict__ vth,
                     const __nv_bfloat16* __restrict__ vtl,
                     const unsigned char* __restrict__ mk,
                     __nv_bfloat16* __restrict__ Oh,
                     __nv_bfloat16* __restrict__ Ol) {
    extern __shared__ __align__(128) unsigned char smem[];
    const uint32_t sbase = smem_u32(smem);

    const int t = threadIdx.x;
    const int lane = t & 31;
    const int w = t >> 5;                 // warp 0..7 -> rows w*16..+15
    const int group = lane >> 2;
    const int tc4 = (lane & 3) * 4;

    const int qb = blockIdx.x;
    const int h  = blockIdx.y;
    const int b  = blockIdx.z;
    const int qBase = b * SLEN + qb * ATQ;
    const int hcol  = h * HD;

    const float qscale = 0.125f * 1.44269504088896340736f;  // 1/8 * log2(e)

    // ---- prologue: Q, then stages 0,1 ----
#pragma unroll
    for (int i = 0; i < 4; i++) {
        int id = t + 256 * i;
        int row = id >> 3;
        int c = id & 7;
        uint32_t soff = (uint32_t)(row * ASHB + c * 16);
        cp16(sbase + AQ_H + soff, qh + (size_t)(qBase + row) * DIM + hcol + c * 8);
        cp16(sbase + AQ_L + soff, ql + (size_t)(qBase + row) * DIM + hcol + c * 8);
    }
    cp_commit();
    attn_load_stage(sbase, kh, kl, vth, vtl, mk, b, hcol, 0, t);
    attn_load_stage(sbase, kh, kl, vth, vtl, mk, b, hcol, 1, t);

    float o[8][4];
    float m_i[2], l_i[2];
#pragma unroll
    for (int g = 0; g < 8; g++)
#pragma unroll
        for (int r = 0; r < 4; r++) o[g][r] = 0.0f;
    m_i[0] = m_i[1] = -1e30f;
    l_i[0] = l_i[1] = 0.0f;

    const int NT = SLEN / ATK;   // 16
    for (int kb = 0; kb < NT; kb++) {
        if (kb == NT - 1) cp_wait<0>(); else cp_wait<1>();
        __syncthreads();

        const unsigned char* stg = smem + AST0 + (kb & 1) * ASTAGE_BYTES;
        const unsigned char* pKh = stg + AK_H;
        const unsigned char* pKl = stg + AK_L;
        const unsigned char* pVh = stg + AV_H;
        const unsigned char* pVl = stg + AV_L;
        const float* madd =
            reinterpret_cast<const float*>(smem + AMSK + (kb & 1) * 256);

        // ---- S = Q K^T (bf16x3) ----
        float s[8][4];
#pragma unroll
        for (int g = 0; g < 8; g++)
#pragma unroll
            for (int r = 0; r < 4; r++) s[g][r] = 0.0f;

        const unsigned char* pQh = smem + AQ_H;
        const unsigned char* pQl = smem + AQ_L;
#pragma unroll
        for (int k = 0; k < 4; k++) {
            const int cb = tc4 + k * 32;
            uint32_t ah[4], al[4];
            int abase = (w * 16 + group) * ASHB + cb;
            ah[0] = *(const uint32_t*)(pQh + abase);
            ah[1] = *(const uint32_t*)(pQh + abase + 8 * ASHB);
            ah[2] = *(const uint32_t*)(pQh + abase + 16);
            ah[3] = *(const uint32_t*)(pQh + abase + 8 * ASHB + 16);
            al[0] = *(const uint32_t*)(pQl + abase);
            al[1] = *(const uint32_t*)(pQl + abase + 8 * ASHB);
            al[2] = *(const uint32_t*)(pQl + abase + 16);
            al[3] = *(const uint32_t*)(pQl + abase + 8 * ASHB + 16);
#pragma unroll
            for (int g = 0; g < 8; g++) {
                int bbase = (g * 8 + group) * ASHB + cb;
                uint32_t bh[2], bl[2];
                bh[0] = *(const uint32_t*)(pKh + bbase);
                bh[1] = *(const uint32_t*)(pKh + bbase + 16);
                bl[0] = *(const uint32_t*)(pKl + bbase);
                bl[1] = *(const uint32_t*)(pKl + bbase + 16);
                mma_bf16(s[g], ah, bh);
                mma_bf16(s[g], ah, bl);
                mma_bf16(s[g], al, bh);
            }
        }

        // ---- scale + mask + online softmax, pack P into registers ----
#pragma unroll
        for (int g = 0; g < 8; g++) {
            float2 ma = *reinterpret_cast<const float2*>(
                &madd[g * 8 + (lane & 3) * 2]);
            s[g][0] = fmaf(s[g][0], qscale, ma.x);
            s[g][1] = fmaf(s[g][1], qscale, ma.y);
            s[g][2] = fmaf(s[g][2], qscale, ma.x);
            s[g][3] = fmaf(s[g][3], qscale, ma.y);
        }
        float mx0 = -1e30f, mx1 = -1e30f;
#pragma unroll
        for (int g = 0; g < 8; g++) {
            mx0 = fmaxf(mx0, fmaxf(s[g][0], s[g][1]));
            mx1 = fmaxf(mx1, fmaxf(s[g][2], s[g][3]));
        }
        mx0 = fmaxf(mx0, __shfl_xor_sync(0xffffffffu, mx0, 1));
        mx0 = fmaxf(mx0, __shfl_xor_sync(0xffffffffu, mx0, 2));
        mx1 = fmaxf(mx1, __shfl_xor_sync(0xffffffffu, mx1, 1));
        mx1 = fmaxf(mx1, __shfl_xor_sync(0xffffffffu, mx1, 2));
        float mn0 = fmaxf(m_i[0], mx0);
        float mn1 = fmaxf(m_i[1], mx1);
        float corr0 = exp2f(m_i[0] - mn0);
        float corr1 = exp2f(m_i[1] - mn1);
        m_i[0] = mn0; m_i[1] = mn1;

        // P fragments in registers: kc = g>>1; g even -> a0,a1; g odd -> a2,a3
        uint32_t pah[4][4], pal[4][4];
        float sum0 = 0.0f, sum1 = 0.0f;
#pragma unroll
        for (int g = 0; g < 8; g++) {
            float p0 = exp2f(s[g][0] - mn0);
            float p1 = exp2f(s[g][1] - mn0);
            float p2 = exp2f(s[g][2] - mn1);
            float p3 = exp2f(s[g][3] - mn1);
            sum0 += p0 + p1;
            sum1 += p2 + p3;
            const int kc = g >> 1;
            const int o2 = (g & 1) * 2;
            pah[kc][o2 + 0] = pack_bf16x2(p0, p1);
            pah[kc][o2 + 1] = pack_bf16x2(p2, p3);
            pal[kc][o2 + 0] = pack_bf16x2(bf16_residual(p0), bf16_residual(p1));
            pal[kc][o2 + 1] = pack_bf16x2(bf16_residual(p2), bf16_residual(p3));
        }
        sum0 += __shfl_xor_sync(0xffffffffu, sum0, 1);
        sum0 += __shfl_xor_sync(0xffffffffu, sum0, 2);
        sum1 += __shfl_xor_sync(0xffffffffu, sum1, 1);
        sum1 += __shfl_xor_sync(0xffffffffu, sum1, 2);
        l_i[0] = l_i[0] * corr0 + sum0;
        l_i[1] = l_i[1] * corr1 + sum1;
#pragma unroll
        for (int g = 0; g < 8; g++) {
            o[g][0] *= corr0; o[g][1] *= corr0;
            o[g][2] *= corr1; o[g][3] *= corr1;
        }

        // ---- O += P Vt (bf16x3), A-frags from registers ----
#pragma unroll
        for (int kc = 0; kc < 4; kc++) {
            const int cb = tc4 + kc * 32;
#pragma unroll
            for (int d = 0; d < 8; d++) {
                int bbase = (d * 8 + group) * ASHB + cb;
                uint32_t bh[2], bl[2];
                bh[0] = *(const uint32_t*)(pVh + bbase);
                bh[1] = *(const uint32_t*)(pVh + bbase + 16);
                bl[0] = *(const uint32_t*)(pVl + bbase);
                bl[1] = *(const uint32_t*)(pVl + bbase + 16);
                mma_bf16(o[d], pah[kc], bh);
                mma_bf16(o[d], pah[kc], bl);
                mma_bf16(o[d], pal[kc], bh);
            }
        }
        __syncthreads();   // all warps done reading this stage

        if (kb + 2 < NT)
            attn_load_stage(sbase, kh, kl, vth, vtl, mk, b, hcol, kb + 2, t);
    }

    // ---- finalize: O / l, split-store bf16 ----
    float inv0 = 1.0f / l_i[0];
    float inv1 = 1.0f / l_i[1];
    const int gr0 = qBase + w * 16 + group;
#pragma unroll
    for (int g = 0; g < 8; g++) {
        int col = hcol + g * 8 + (lane & 3) * 2;
        float v0 = o[g][0] * inv0, v1 = o[g][1] * inv0;
        float v2 = o[g][2] * inv1, v3 = o[g][3] * inv1;
        *reinterpret_cast<uint32_t*>(&Oh[(size_t)gr0 * DIM + col]) =
            pack_bf16x2(v0, v1);
        *reinterpret_cast<uint32_t*>(&Ol[(size_t)gr0 * DIM + col]) =
            pack_bf16x2(bf16_residual(v0), bf16_residual(v1));
        *reinterpret_cast<uint32_t*>(&Oh[(size_t)(gr0 + 8) * DIM + col]) =
            pack_bf16x2(v2, v3);
        *reinterpret_cast<uint32_t*>(&Ol[(size_t)(gr0 + 8) * DIM + col]) =
            pack_bf16x2(bf16_residual(v2), bf16_residual(v3));
    }
}

// ---------------------------------------------------------------------------
// Launcher
// ---------------------------------------------------------------------------
extern "C" void kernel_launch(void* const* d_in, const int* in_sizes, int n_in,
                              void* d_out, int out_size) {
    (void)in_sizes; (void)n_in; (void)out_size;
    const float* x          = (const float*)d_in[0];
    const unsigned char* mk = (const unsigned char*)d_in[1];
    const float* w[4] = {(const float*)d_in[2], (const float*)d_in[4],
                         (const float*)d_in[6], (const float*)d_in[8]};
    const float* bq = (const float*)d_in[3];
    const float* bk = (const float*)d_in[5];
    const float* bv = (const float*)d_in[7];
    const float* bo = (const float*)d_in[9];
    float* out = (float*)d_out;

    __nv_bfloat16 *xh, *xl, *qhp, *qlp, *khp, *klp, *vhp, *vlp;
    __nv_bfloat16 *vth, *vtl, *ah, *al, *wth, *wtl;
    cudaGetSymbolAddress((void**)&xh, g_x_hi);
    cudaGetSymbolAddress((void**)&xl, g_x_lo);
    cudaGetSymbolAddress((void**)&qhp, g_q_hi);
    cudaGetSymbolAddress((void**)&qlp, g_q_lo);
    cudaGetSymbolAddress((void**)&khp, g_k_hi);
    cudaGetSymbolAddress((void**)&klp, g_k_lo);
    cudaGetSymbolAddress((void**)&vhp, g_v_hi);
    cudaGetSymbolAddress((void**)&vlp, g_v_lo);
    cudaGetSymbolAddress((void**)&vth, g_vt_hi);
    cudaGetSymbolAddress((void**)&vtl, g_vt_lo);
    cudaGetSymbolAddress((void**)&ah, g_a_hi);
    cudaGetSymbolAddress((void**)&al, g_a_lo);
    cudaGetSymbolAddress((void**)&wth, g_wt_hi);
    cudaGetSymbolAddress((void**)&wtl, g_wt_lo);

    const int n4 = M_ROWS * DIM / 4;
    split_kernel<<<(n4 + 255) / 256, 256>>>(x, xh, xl, n4);
    dim3 tgrid(DIM / 32, DIM / 32);
    for (int i = 0; i < 4; i++)
        transpose_split_kernel<<<tgrid, dim3(32, 8)>>>(
            w[i], wth + (size_t)i * DIM * DIM, wtl + (size_t)i * DIM * DIM);

    cudaFuncSetAttribute(mma_gemm_kernel<0>,
                         cudaFuncAttributeMaxDynamicSharedMemorySize, GEMM_SMEM);
    cudaFuncSetAttribute(mma_gemm_kernel<1>,
                         cudaFuncAttributeMaxDynamicSharedMemorySize, GEMM_SMEM);
    dim3 ggrid(DIM / BN, M_ROWS / BM);

    mma_gemm_kernel<1><<<ggrid, 256, GEMM_SMEM>>>(
        xh, xl, wth + 0 * (size_t)DIM * DIM, wtl + 0 * (size_t)DIM * DIM, bq,
        nullptr, qhp, qlp);
    mma_gemm_kernel<1><<<ggrid, 256, GEMM_SMEM>>>(
        xh, xl, wth + 1 * (size_t)DIM * DIM, wtl + 1 * (size_t)DIM * DIM, bk,
        nullptr, khp, klp);
    mma_gemm_kernel<1><<<ggrid, 256, GEMM_SMEM>>>(
        xh, xl, wth + 2 * (size_t)DIM * DIM, wtl + 2 * (size_t)DIM * DIM, bv,
        nullptr, vhp, vlp);

    transpose_v_kernel<<<dim3(32, 32, 4), dim3(32, 8)>>>(vhp, vlp, vth, vtl);

    cudaFuncSetAttribute(attn_mma_kernel,
                         cudaFuncAttributeMaxDynamicSharedMemorySize, ATTN_SMEM);
    attn_mma_kernel<<<dim3(SLEN / ATQ, NH, 4), 256, ATTN_SMEM>>>(
        qhp, qlp, khp, klp, vth, vtl, mk, ah, al);

    mma_gemm_kernel<0><<<ggrid, 256, GEMM_SMEM>>>(
        ah, al, wth + 3 * (size_t)DIM * DIM, wtl + 3 * (size_t)DIM * DIM, bo,
        out, nullptr, nullptr);
}